// round 9
// baseline (speedup 1.0000x reference)
#include <cuda_runtime.h>
#include <cuda_bf16.h>
#include <cstdint>

#define NB 16
#define NT 9
#define NYX 256
#define SP 65536
#define C1 10
#define C2 20
#define C3 54

#define OFF_XOUT 0
#define OFF_KAP  16
#define OFF_M    9437200
#define OFF_H    28311568

typedef unsigned long long u64;

__device__ float g_p1[NB * C1 * SP];
__device__ float g_p2[NB * C2 * SP];
__device__ float g_p3[NB * C3 * SP];
__device__ float g_xg[NB * NT * SP];
__device__ float g_w [NB * NT * SP];
__device__ float g_v [NB * NT * SP];
__device__ float g_kg [NB * NT * SP];
__device__ float g_m1 [NB * NT * SP];
__device__ float g_m2 [NB * NT * SP];
__device__ float g_h11[NB * NT * SP];
__device__ float g_hxy[NB * NT * SP];
__device__ float g_h22[NB * NT * SP];
__device__ float g_part[NB * 160];
// weight fragments for all 3 convs: 127 slots x 32 lanes x {hi,lo} float4
// slot layout: conv1: 0..10 (MT=1,KS=11); conv2: 11..34 (MT=2,KS=12); conv3: 35..126 (MT=4,KS=23)
__device__ float4 g_wfrag[127 * 32 * 2];

__device__ __forceinline__ float sp10(float x) {
    float z = 10.0f * x;
    return (fmaxf(z, 0.0f) + log1pf(expf(-fabsf(z)))) * 0.1f;
}
__device__ __forceinline__ float to_tf32(float x) {
    uint32_t r; asm("cvt.rna.tf32.f32 %0, %1;" : "=r"(r) : "f"(x));
    return __uint_as_float(r);
}
__device__ __forceinline__ void mma_tf32(float* d, const uint32_t* a, const uint32_t* b) {
    asm("mma.sync.aligned.m16n8k8.row.col.f32.tf32.tf32.f32 "
        "{%0,%1,%2,%3}, {%4,%5,%6,%7}, {%8,%9}, {%0,%1,%2,%3};"
        : "+f"(d[0]), "+f"(d[1]), "+f"(d[2]), "+f"(d[3])
        : "r"(a[0]), "r"(a[1]), "r"(a[2]), "r"(a[3]), "r"(b[0]), "r"(b[1]));
}

// ---------------------------------------------------------------------------
// Prep: all conv weights -> fragment-ordered hi/lo TF32 split (127*32 threads)
// ---------------------------------------------------------------------------
__global__ void prep_w_k(const float* __restrict__ w1,
                         const float* __restrict__ w2,
                         const float* __restrict__ w3) {
    int idx = blockIdx.x * blockDim.x + threadIdx.x;
    if (idx >= 127 * 32) return;
    int lane = idx & 31;
    int slot = idx >> 5;
    const float* w; int K, COUT, mt, ks;
    if (slot < 11)      { w = w1; K = 81;  COUT = C1; mt = 0;                ks = slot; }
    else if (slot < 35) { w = w2; K = 90;  COUT = C2; int s = slot - 11; mt = s / 12; ks = s % 12; }
    else                { w = w3; K = 180; COUT = C3; int s = slot - 35; mt = s / 23; ks = s % 23; }
    int g = lane >> 2, tig = lane & 3;
    float hi[4], lo[4];
#pragma unroll
    for (int i = 0; i < 4; i++) {
        int row = mt * 16 + g + (i & 1) * 8;
        int k   = ks * 8 + tig + (i >> 1) * 4;
        float wv = (row < COUT && k < K) ? w[row * K + k] : 0.0f;
        float h = to_tf32(wv);
        hi[i] = h;
        lo[i] = to_tf32(wv - h);
    }
    int base = (slot * 32 + lane) * 2;
    g_wfrag[base]     = make_float4(hi[0], hi[1], hi[2], hi[3]);
    g_wfrag[base + 1] = make_float4(lo[0], lo[1], lo[2], lo[3]);
}

// ---------------------------------------------------------------------------
// Generic conv3x3 via tensor cores (implicit GEMM, tf32 3-pass).
// Block (32,8): one output row (256 px), all couts, one batch.
// K = CIN*9 padded to KS*8. smem tile: (CIN*3+1) rows x 258 (+1 zero row).
// Warp w: n-tiles 4w..4w+3 (8 px each). acc[MT][4][4].
// ---------------------------------------------------------------------------
template <int CIN, bool RELU_IN, int MT, int KS, int COUT, int WOFF, int MAXB>
__global__ void __launch_bounds__(256, MAXB)
conv_mma_k(const float* __restrict__ in, float* __restrict__ out) {
    extern __shared__ float sh[];
    const int TS = 258;
    const int ZR = CIN * 3;                  // zero row index
    float* tile = sh;                        // (CIN*3+1)*258 floats
    int*   koff = (int*)(sh + (ZR + 1) * TS);// KS*8 ints

    const int b  = blockIdx.z;
    const int y0 = blockIdx.y;
    const int tid = threadIdx.y * 32 + threadIdx.x;

    const float* inb = in + (size_t)b * CIN * SP;
    for (int idx = tid; idx < CIN * 3 * 258; idx += 256) {
        int c  = idx % 258;
        int rr = (idx / 258) % 3;
        int ci = idx / 774;
        int gy = y0 - 1 + rr;
        int gx = c - 1;
        float v = 0.0f;
        if (gy >= 0 && gy < NYX && gx >= 0 && gx < NYX) {
            v = inb[ci * SP + gy * NYX + gx];
            if (RELU_IN) v = fmaxf(v, 0.0f);
        }
        tile[(ci * 3 + rr) * TS + c] = v;
    }
    for (int i = tid; i < 258; i += 256) tile[ZR * TS + i] = 0.0f;
    for (int k = tid; k < KS * 8; k += 256) {
        if (k < CIN * 9) {
            int ci = k / 9, r = k % 9;
            koff[k] = (ci * 3 + r / 3) * TS + (r % 3);
        } else {
            koff[k] = ZR * TS;
        }
    }
    __syncthreads();

    const int warp = threadIdx.y;
    const int lane = threadIdx.x;
    const int g = lane >> 2, tig = lane & 3;
    const int nbase = warp * 32;

    float acc[MT][4][4];
#pragma unroll
    for (int m = 0; m < MT; m++)
#pragma unroll
        for (int n = 0; n < 4; n++)
#pragma unroll
            for (int q = 0; q < 4; q++) acc[m][n][q] = 0.0f;

    for (int ks = 0; ks < KS; ks++) {
        uint32_t bhi[4][2], blo[4][2];
        int o0 = koff[ks * 8 + tig];
        int o1 = koff[ks * 8 + tig + 4];
#pragma unroll
        for (int nt = 0; nt < 4; nt++) {
            int n = nbase + nt * 8 + g;
            float x0 = tile[o0 + n];
            float x1 = tile[o1 + n];
            float h0 = to_tf32(x0), h1 = to_tf32(x1);
            bhi[nt][0] = __float_as_uint(h0);
            bhi[nt][1] = __float_as_uint(h1);
            blo[nt][0] = __float_as_uint(to_tf32(x0 - h0));
            blo[nt][1] = __float_as_uint(to_tf32(x1 - h1));
        }
#pragma unroll
        for (int mt = 0; mt < MT; mt++) {
            int base = ((WOFF + mt * KS + ks) * 32 + lane) * 2;
            float4 ah = g_wfrag[base];
            float4 al = g_wfrag[base + 1];
            uint32_t ahi[4] = { __float_as_uint(ah.x), __float_as_uint(ah.y),
                                __float_as_uint(ah.z), __float_as_uint(ah.w) };
            uint32_t alo[4] = { __float_as_uint(al.x), __float_as_uint(al.y),
                                __float_as_uint(al.z), __float_as_uint(al.w) };
#pragma unroll
            for (int nt = 0; nt < 4; nt++) {
                mma_tf32(acc[mt][nt], ahi, bhi[nt]);
                mma_tf32(acc[mt][nt], ahi, blo[nt]);
                mma_tf32(acc[mt][nt], alo, bhi[nt]);
            }
        }
    }

#pragma unroll
    for (int mt = 0; mt < MT; mt++) {
        int co0 = mt * 16 + g;
#pragma unroll
        for (int nt = 0; nt < 4; nt++) {
            int px = nbase + nt * 8 + 2 * tig;
            float* op = out + ((size_t)b * COUT + co0) * SP + (size_t)y0 * NYX + px;
            if (co0 < COUT)
                *reinterpret_cast<float2*>(op) = make_float2(acc[mt][nt][0], acc[mt][nt][1]);
            if (co0 + 8 < COUT)
                *reinterpret_cast<float2*>(op + (size_t)8 * SP) = make_float2(acc[mt][nt][2], acc[mt][nt][3]);
        }
    }
}

// ---------------------------------------------------------------------------
__global__ void epiA_scramble_k(float* __restrict__ out) {
    __shared__ float shk[2304], shm1[2304], shm2[2304];
    int b = blockIdx.y;
    int chunk = blockIdx.x;
    int L0 = chunk * 2304;
    int s0 = chunk * 256;
    const float* src = g_p3 + (size_t)b * C3 * SP;
    float* okap = out + OFF_KAP + (size_t)b * 9 * SP;
    float* om   = out + OFF_M   + (size_t)b * 18 * SP;
#pragma unroll
    for (int it = 0; it < 9; ++it) {
        int i = it * 256 + threadIdx.x;
        int L = L0 + i;
        float k  = sp10(src[L]);
        float m1 = src[9 * SP + L];
        float m2 = src[18 * SP + L];
        shk[i] = k; shm1[i] = m1; shm2[i] = m2;
        okap[L] = k;
        om[L] = m1;
        om[9 * SP + L] = m2;
    }
    __syncthreads();
#pragma unroll
    for (int it = 0; it < 9; ++it) {
        int i = it * 256 + threadIdx.x;
        int so = i & 255;
        int t = i >> 8;
        int si = 9 * so + t;
        size_t dst = ((size_t)b * 9 + t) * SP + s0 + so;
        g_kg[dst] = shk[si];
        g_m1[dst] = shm1[si];
        g_m2[dst] = shm2[si];
    }
}

// ---------------------------------------------------------------------------
__global__ void epiH_k(float* __restrict__ out) {
    int gid = blockIdx.x * blockDim.x + threadIdx.x;
    int b = gid >> 16;
    int s = gid & (SP - 1);
    const float* pb = g_p3 + (size_t)b * C3 * SP + s;
    float gm[NT], vx[NT], vy[NT];
#pragma unroll
    for (int t = 0; t < NT; t++) {
        gm[t] = sp10(pb[(size_t)(27 + t) * SP]);
        vx[t] = pb[(size_t)(36 + t) * SP];
        vy[t] = pb[(size_t)(45 + t) * SP];
    }
    const size_t PLANE = (size_t)SP * NT;
    size_t base = OFF_H + (size_t)b * 4 * PLANE + (size_t)s * NT;
    size_t pb2 = (size_t)b * NT * SP + s;
#pragma unroll
    for (int t = 0; t < NT; t++) {
        float h11 = gm[t] + vx[t] * vx[t];
        out[base + t] = h11;
        g_h11[pb2 + (size_t)t * SP] = h11;
    }
#pragma unroll
    for (int t = 0; t < NT; t++) {
        float xy = vx[t] * vy[t];
        out[base + PLANE + t]     = xy;
        out[base + 2 * PLANE + t] = xy;
        g_hxy[pb2 + (size_t)t * SP] = xy;
    }
#pragma unroll
    for (int t = 0; t < NT; t++) {
        float h22 = gm[t] + vy[t] * vy[t];
        out[base + 3 * PLANE + t] = h22;
        g_h22[pb2 + (size_t)t * SP] = h22;
    }
}

// ---------------------------------------------------------------------------
__global__ void transpose_k(const float* __restrict__ x) {
    __shared__ float tile[32][33];
    int b = blockIdx.z / NT, t = blockIdx.z % NT;
    const float* xb = x + ((size_t)b * NT + t) * SP;
    float* og = g_xg + ((size_t)b * NT + t) * SP;
    int Y0 = blockIdx.y * 32, X0 = blockIdx.x * 32;
#pragma unroll
    for (int k = 0; k < 4; k++) {
        int row = threadIdx.y + k * 8;
        tile[row][threadIdx.x] = xb[(size_t)(Y0 + row) * NYX + X0 + threadIdx.x];
    }
    __syncthreads();
#pragma unroll
    for (int k = 0; k < 4; k++) {
        int row = threadIdx.y + k * 8;
        og[(size_t)(X0 + row) * NYX + Y0 + threadIdx.x] = tile[threadIdx.x][row];
    }
}

// ---------------------------------------------------------------------------
__global__ void applyM_k(const float* __restrict__ u, float* __restrict__ og) {
    __shared__ float tile[10][36];
    int bt = blockIdx.z;
    int A0 = blockIdx.y * 8, C0 = blockIdx.x * 32;
    const float* ub = u + (size_t)bt * SP;
    int tid = threadIdx.y * 32 + threadIdx.x;
    for (int i = tid; i < 10 * 34; i += 256) {
        int rr = i / 34, cc = i % 34;
        int A = A0 - 1 + rr, C = C0 - 1 + cc;
        tile[rr][cc] = (A >= 0 && A < NYX && C >= 0 && C < NYX)
                       ? ub[(size_t)A * NYX + C] : 0.0f;
    }
    __syncthreads();
    int a = threadIdx.y, c = threadIdx.x;
    float u0 = tile[a + 1][c + 1];
    float xp = tile[a + 2][c + 1], xm = tile[a][c + 1];
    float yp = tile[a + 1][c + 2], ym = tile[a + 1][c];
    float pp = tile[a + 2][c + 2], pm = tile[a + 2][c];
    float mp = tile[a][c + 2],     mm = tile[a][c];
    float dx  = 0.5f * (xp - xm);
    float dy  = 0.5f * (yp - ym);
    float dxx = xp - 2.0f * u0 + xm;
    float dyy = yp - 2.0f * u0 + ym;
    float dxy = 0.25f * (pp - pm - mp + mm);

    int s = (A0 + a) * NYX + (C0 + c);
    size_t pl = (size_t)bt * SP + s;
    float kap = g_kg[pl];
    float m1  = g_m1[pl];
    float m2  = g_m2[pl];
    float h11 = g_h11[pl];
    float hxy = g_hxy[pl];
    float h22 = g_h22[pl];

    float r = u0 + kap * kap * u0 + m1 * dx + m2 * dy
            - (h11 * dxx + 2.0f * hxy * dxy + h22 * dyy);
    og[pl] = r;
}

// ---------------------------------------------------------------------------
__global__ void qx_reduce_k() {
    __shared__ float sm[256];
    int b = blockIdx.y;
    size_t base = (size_t)blockIdx.x * 4096;
    const float* xb = g_xg + (size_t)b * NT * SP;
    const float* wb = g_w  + (size_t)b * NT * SP;
    const float* vb = g_v  + (size_t)b * NT * SP;
    float sum = 0.0f;
    for (int i = threadIdx.x; i < 4096; i += 256) {
        size_t e = base + i;
        int t = (int)(e >> 16);
        int s = (int)(e & (SP - 1));
        float q;
        if (t == 0)       q = vb[s] - wb[SP + s];
        else if (t == 8)  q = -wb[7 * SP + s] + vb[8 * (size_t)SP + s];
        else              q = -wb[(size_t)(t - 1) * SP + s] + vb[e] + xb[e]
                              - wb[(size_t)(t + 1) * SP + s];
        sum += xb[e] * q;
    }
    sm[threadIdx.x] = sum;
    __syncthreads();
    for (int st = 128; st > 0; st >>= 1) {
        if (threadIdx.x < st) sm[threadIdx.x] += sm[threadIdx.x + st];
        __syncthreads();
    }
    if (threadIdx.x == 0) g_part[b * 160 + blockIdx.x] = sm[0];
}

__global__ void final_reduce_k(float* __restrict__ out) {
    int b = threadIdx.x;
    if (b < NB) {
        float s = 0.0f;
        for (int i = 0; i < 144; i++) s += g_part[b * 160 + i];
        out[OFF_XOUT + b] = s;
    }
}

// ---------------------------------------------------------------------------
extern "C" void kernel_launch(void* const* d_in, const int* in_sizes, int n_in,
                              void* d_out, int out_size) {
    const float* x  = (const float*)d_in[0];
    const float* w1 = (const float*)d_in[4];
    const float* w2 = (const float*)d_in[5];
    const float* w3 = (const float*)d_in[6];
    float* out = (float*)d_out;

    float *p1, *p2, *p3, *xg, *wg, *vg;
    cudaGetSymbolAddress((void**)&p1, g_p1);
    cudaGetSymbolAddress((void**)&p2, g_p2);
    cudaGetSymbolAddress((void**)&p3, g_p3);
    cudaGetSymbolAddress((void**)&xg, g_xg);
    cudaGetSymbolAddress((void**)&wg, g_w);
    cudaGetSymbolAddress((void**)&vg, g_v);

    // conv template instantiations:
    //   conv1: CIN=9,  MT=1, KS=11, WOFF=0,  relu-in
    //   conv2: CIN=10, MT=2, KS=12, WOFF=11, relu-in
    //   conv3: CIN=20, MT=4, KS=23, WOFF=35
    const int smem1 = (9  * 3 + 1) * 258 * 4 + 11 * 8 * 4;   // 28,928
    const int smem2 = (10 * 3 + 1) * 258 * 4 + 12 * 8 * 4;   // 32,376
    const int smem3 = (20 * 3 + 1) * 258 * 4 + 23 * 8 * 4;   // 63,688
    cudaFuncSetAttribute((const void*)conv_mma_k<9,  true,  1, 11, C1, 0,  4>, cudaFuncAttributeMaxDynamicSharedMemorySize, smem1);
    cudaFuncSetAttribute((const void*)conv_mma_k<10, true,  2, 12, C2, 11, 3>, cudaFuncAttributeMaxDynamicSharedMemorySize, smem2);
    cudaFuncSetAttribute((const void*)conv_mma_k<20, false, 4, 23, C3, 35, 2>, cudaFuncAttributeMaxDynamicSharedMemorySize, smem3);

    // 1: weight prep (all convs)
    prep_w_k<<<16, 256>>>(w1, w2, w3);
    // 2,3,4: conv chain (all tensor)
    conv_mma_k<9,  true,  1, 11, C1, 0,  4><<<dim3(1, 256, NB), dim3(32, 8), smem1>>>(x,  p1);
    conv_mma_k<10, true,  2, 12, C2, 11, 3><<<dim3(1, 256, NB), dim3(32, 8), smem2>>>(p1, p2);
    conv_mma_k<20, false, 4, 23, C3, 35, 2><<<dim3(1, 256, NB), dim3(32, 8), smem3>>>(p2, p3);

    // independent of convs
    transpose_k<<<dim3(8, 8, NB * NT), dim3(32, 8)>>>(x);

    // epilogues
    epiH_k<<<(NB * SP) / 256, 256>>>(out);
    epiA_scramble_k<<<dim3(256, NB), 256>>>(out);

    // PDE pipeline
    applyM_k<<<dim3(8, 32, NB * NT), dim3(32, 8)>>>(xg, wg);
    applyM_k<<<dim3(8, 32, NB * NT), dim3(32, 8)>>>(wg, vg);
    qx_reduce_k<<<dim3(144, NB), 256>>>();
    final_reduce_k<<<1, 32>>>(out);
}

// round 10
// speedup vs baseline: 1.1781x; 1.1781x over previous
#include <cuda_runtime.h>
#include <cuda_bf16.h>
#include <cstdint>

#define NB 16
#define NT 9
#define NYX 256
#define SP 65536
#define C1 10
#define C2 20
#define C3 54

#define OFF_XOUT 0
#define OFF_KAP  16
#define OFF_M    9437200
#define OFF_H    28311568

__device__ float g_p1[NB * C1 * SP];
__device__ float g_p2[NB * C2 * SP];
__device__ float g_p3[NB * C3 * SP];
__device__ float g_xg[NB * NT * SP];
__device__ float g_w [NB * NT * SP];
__device__ float g_v [NB * NT * SP];
__device__ float g_kg [NB * NT * SP];
__device__ float g_m1 [NB * NT * SP];
__device__ float g_m2 [NB * NT * SP];
__device__ float g_part[NB * 160];
// bf16 A-fragments (hi,lo uint4 pairs). slots: conv1 0..5 (MT1,KS6),
// conv2 6..17 (MT2,KS6), conv3 18..65 (MT4,KS12). 66 slots x 32 lanes x 2.
__device__ uint4 g_wfrag[66 * 32 * 2];

__device__ __forceinline__ float sp10(float x) {
    float z = 10.0f * x;
    return (fmaxf(z, 0.0f) + log1pf(expf(-fabsf(z)))) * 0.1f;
}
// pack (lo, hi) f32 -> bf16x2 (lo in low half)
__device__ __forceinline__ uint32_t bfpack(float lo, float hi) {
    uint32_t r; asm("cvt.rn.bf16x2.f32 %0, %1, %2;" : "=r"(r) : "f"(hi), "f"(lo));
    return r;
}
__device__ __forceinline__ float bf_lo(uint32_t h) { return __uint_as_float(h << 16); }
__device__ __forceinline__ float bf_hi(uint32_t h) { return __uint_as_float(h & 0xFFFF0000u); }

__device__ __forceinline__ void mma_bf16(float* d, const uint32_t* a, const uint32_t* b) {
    asm("mma.sync.aligned.m16n8k16.row.col.f32.bf16.bf16.f32 "
        "{%0,%1,%2,%3}, {%4,%5,%6,%7}, {%8,%9}, {%0,%1,%2,%3};"
        : "+f"(d[0]), "+f"(d[1]), "+f"(d[2]), "+f"(d[3])
        : "r"(a[0]), "r"(a[1]), "r"(a[2]), "r"(a[3]), "r"(b[0]), "r"(b[1]));
}

// ---------------------------------------------------------------------------
// Prep: weights -> bf16 m16n8k16 A-fragments, hi/lo split.
// a_i: row = mt*16 + g + (i&1)*8 ; kpair = ks*16 + (i>>1)*8 + 2*tig.
// ---------------------------------------------------------------------------
__global__ void prep_w_k(const float* __restrict__ w1,
                         const float* __restrict__ w2,
                         const float* __restrict__ w3) {
    int idx = blockIdx.x * blockDim.x + threadIdx.x;
    if (idx >= 66 * 32) return;
    int lane = idx & 31;
    int slot = idx >> 5;
    const float* w; int K, COUT, mt, ks;
    if (slot < 6)       { w = w1; K = 81;  COUT = C1; mt = 0;               ks = slot; }
    else if (slot < 18) { w = w2; K = 90;  COUT = C2; int s = slot - 6;  mt = s / 6;  ks = s % 6; }
    else                { w = w3; K = 180; COUT = C3; int s = slot - 18; mt = s / 12; ks = s % 12; }
    int g = lane >> 2, tig = lane & 3;
    uint32_t hi[4], lo[4];
#pragma unroll
    for (int i = 0; i < 4; i++) {
        int row = mt * 16 + g + (i & 1) * 8;
        int k   = ks * 16 + (i >> 1) * 8 + 2 * tig;
        float w0 = (row < COUT && k     < K) ? w[row * K + k]     : 0.0f;
        float w1v = (row < COUT && k + 1 < K) ? w[row * K + k + 1] : 0.0f;
        uint32_t h = bfpack(w0, w1v);
        hi[i] = h;
        lo[i] = bfpack(w0 - bf_lo(h), w1v - bf_hi(h));
    }
    int base = (slot * 32 + lane) * 2;
    g_wfrag[base]     = make_uint4(hi[0], hi[1], hi[2], hi[3]);
    g_wfrag[base + 1] = make_uint4(lo[0], lo[1], lo[2], lo[3]);
}

// ---------------------------------------------------------------------------
// Generic conv3x3 via bf16 m16n8k16 tensor MMA, 3-pass (hi/lo split).
// Block (32,8): one output row (256 px), all couts, one batch.
// K = CIN*9 padded to KS*16. smem tile (CIN*3+1) x 258 + koff[KS*16].
// ---------------------------------------------------------------------------
template <int CIN, bool RELU_IN, int MT, int KS, int COUT, int WOFF, int MAXB>
__global__ void __launch_bounds__(256, MAXB)
conv_mma_k(const float* __restrict__ in, float* __restrict__ out) {
    extern __shared__ float sh[];
    const int TS = 258;
    const int ZR = CIN * 3;
    float* tile = sh;
    int*   koff = (int*)(sh + (ZR + 1) * TS);

    const int b  = blockIdx.z;
    const int y0 = blockIdx.y;
    const int tid = threadIdx.y * 32 + threadIdx.x;

    const float* inb = in + (size_t)b * CIN * SP;
    for (int idx = tid; idx < CIN * 3 * 258; idx += 256) {
        int c  = idx % 258;
        int rr = (idx / 258) % 3;
        int ci = idx / 774;
        int gy = y0 - 1 + rr;
        int gx = c - 1;
        float v = 0.0f;
        if (gy >= 0 && gy < NYX && gx >= 0 && gx < NYX) {
            v = inb[ci * SP + gy * NYX + gx];
            if (RELU_IN) v = fmaxf(v, 0.0f);
        }
        tile[(ci * 3 + rr) * TS + c] = v;
    }
    for (int i = tid; i < 258; i += 256) tile[ZR * TS + i] = 0.0f;
    for (int k = tid; k < KS * 16; k += 256) {
        if (k < CIN * 9) {
            int ci = k / 9, r = k % 9;
            koff[k] = (ci * 3 + r / 3) * TS + (r % 3);
        } else {
            koff[k] = ZR * TS;
        }
    }
    __syncthreads();

    const int warp = threadIdx.y;
    const int lane = threadIdx.x;
    const int g = lane >> 2, tig = lane & 3;
    const int nbase = warp * 32;

    float acc[MT][4][4];
#pragma unroll
    for (int m = 0; m < MT; m++)
#pragma unroll
        for (int n = 0; n < 4; n++)
#pragma unroll
            for (int q = 0; q < 4; q++) acc[m][n][q] = 0.0f;

    for (int ks = 0; ks < KS; ks++) {
        // B fragments: rows (2tig,2tig+1) -> b0, (8+2tig,8+2tig+1) -> b1
        int o00 = koff[ks * 16 + 2 * tig];
        int o01 = koff[ks * 16 + 2 * tig + 1];
        int o10 = koff[ks * 16 + 8 + 2 * tig];
        int o11 = koff[ks * 16 + 8 + 2 * tig + 1];
        uint32_t bhi[4][2], blo[4][2];
#pragma unroll
        for (int nt = 0; nt < 4; nt++) {
            int n = nbase + nt * 8 + g;
            float x00 = tile[o00 + n], x01 = tile[o01 + n];
            float x10 = tile[o10 + n], x11 = tile[o11 + n];
            uint32_t h0 = bfpack(x00, x01);
            uint32_t h1 = bfpack(x10, x11);
            bhi[nt][0] = h0;
            bhi[nt][1] = h1;
            blo[nt][0] = bfpack(x00 - bf_lo(h0), x01 - bf_hi(h0));
            blo[nt][1] = bfpack(x10 - bf_lo(h1), x11 - bf_hi(h1));
        }
#pragma unroll
        for (int mt = 0; mt < MT; mt++) {
            int base = ((WOFF + mt * KS + ks) * 32 + lane) * 2;
            uint4 ah = g_wfrag[base];
            uint4 al = g_wfrag[base + 1];
            uint32_t ahi[4] = { ah.x, ah.y, ah.z, ah.w };
            uint32_t alo[4] = { al.x, al.y, al.z, al.w };
#pragma unroll
            for (int nt = 0; nt < 4; nt++) {
                mma_bf16(acc[mt][nt], ahi, bhi[nt]);
                mma_bf16(acc[mt][nt], ahi, blo[nt]);
                mma_bf16(acc[mt][nt], alo, bhi[nt]);
            }
        }
    }

#pragma unroll
    for (int mt = 0; mt < MT; mt++) {
        int co0 = mt * 16 + g;
#pragma unroll
        for (int nt = 0; nt < 4; nt++) {
            int px = nbase + nt * 8 + 2 * tig;
            float* op = out + ((size_t)b * COUT + co0) * SP + (size_t)y0 * NYX + px;
            if (co0 < COUT)
                *reinterpret_cast<float2*>(op) = make_float2(acc[mt][nt][0], acc[mt][nt][1]);
            if (co0 + 8 < COUT)
                *reinterpret_cast<float2*>(op + (size_t)8 * SP) = make_float2(acc[mt][nt][2], acc[mt][nt][3]);
        }
    }
}

// ---------------------------------------------------------------------------
// kappa_r + m_r outputs AND kg/m1/m2 plane grids, via smem staging.
// ---------------------------------------------------------------------------
__global__ void epiA_scramble_k(float* __restrict__ out) {
    __shared__ float shk[2304], shm1[2304], shm2[2304];
    int b = blockIdx.y;
    int chunk = blockIdx.x;
    int L0 = chunk * 2304;
    int s0 = chunk * 256;
    const float* src = g_p3 + (size_t)b * C3 * SP;
    float* okap = out + OFF_KAP + (size_t)b * 9 * SP;
    float* om   = out + OFF_M   + (size_t)b * 18 * SP;
#pragma unroll
    for (int it = 0; it < 9; ++it) {
        int i = it * 256 + threadIdx.x;
        int L = L0 + i;
        float k  = sp10(src[L]);
        float m1 = src[9 * SP + L];
        float m2 = src[18 * SP + L];
        shk[i] = k; shm1[i] = m1; shm2[i] = m2;
        okap[L] = k;
        om[L] = m1;
        om[9 * SP + L] = m2;
    }
    __syncthreads();
#pragma unroll
    for (int it = 0; it < 9; ++it) {
        int i = it * 256 + threadIdx.x;
        int so = i & 255;
        int t = i >> 8;
        int si = 9 * so + t;
        size_t dst = ((size_t)b * 9 + t) * SP + s0 + so;
        g_kg[dst] = shk[si];
        g_m1[dst] = shm1[si];
        g_m2[dst] = shm2[si];
    }
}

// ---------------------------------------------------------------------------
// H_r output only (h-grids now computed in applyM directly from p3).
// ---------------------------------------------------------------------------
__global__ void epiH_k(float* __restrict__ out) {
    int gid = blockIdx.x * blockDim.x + threadIdx.x;
    int b = gid >> 16;
    int s = gid & (SP - 1);
    const float* pb = g_p3 + (size_t)b * C3 * SP + s;
    float gm[NT], vx[NT], vy[NT];
#pragma unroll
    for (int t = 0; t < NT; t++) {
        gm[t] = sp10(pb[(size_t)(27 + t) * SP]);
        vx[t] = pb[(size_t)(36 + t) * SP];
        vy[t] = pb[(size_t)(45 + t) * SP];
    }
    const size_t PLANE = (size_t)SP * NT;
    size_t base = OFF_H + (size_t)b * 4 * PLANE + (size_t)s * NT;
#pragma unroll
    for (int t = 0; t < NT; t++) out[base + t] = gm[t] + vx[t] * vx[t];
#pragma unroll
    for (int t = 0; t < NT; t++) {
        float xy = vx[t] * vy[t];
        out[base + PLANE + t]     = xy;
        out[base + 2 * PLANE + t] = xy;
    }
#pragma unroll
    for (int t = 0; t < NT; t++) out[base + 3 * PLANE + t] = gm[t] + vy[t] * vy[t];
}

// ---------------------------------------------------------------------------
__global__ void transpose_k(const float* __restrict__ x) {
    __shared__ float tile[32][33];
    int b = blockIdx.z / NT, t = blockIdx.z % NT;
    const float* xb = x + ((size_t)b * NT + t) * SP;
    float* og = g_xg + ((size_t)b * NT + t) * SP;
    int Y0 = blockIdx.y * 32, X0 = blockIdx.x * 32;
#pragma unroll
    for (int k = 0; k < 4; k++) {
        int row = threadIdx.y + k * 8;
        tile[row][threadIdx.x] = xb[(size_t)(Y0 + row) * NYX + X0 + threadIdx.x];
    }
    __syncthreads();
#pragma unroll
    for (int k = 0; k < 4; k++) {
        int row = threadIdx.y + k * 8;
        og[(size_t)(X0 + row) * NYX + Y0 + threadIdx.x] = tile[threadIdx.x][row];
    }
}

// ---------------------------------------------------------------------------
// M(u): kap/m1/m2 from scramble grids; h11/hxy/h22 recomputed from p3.
// ---------------------------------------------------------------------------
__global__ void applyM_k(const float* __restrict__ u, float* __restrict__ og) {
    __shared__ float tile[10][36];
    int bt = blockIdx.z;
    int b = bt / NT, t = bt % NT;
    int A0 = blockIdx.y * 8, C0 = blockIdx.x * 32;
    const float* ub = u + (size_t)bt * SP;
    int tid = threadIdx.y * 32 + threadIdx.x;
    for (int i = tid; i < 10 * 34; i += 256) {
        int rr = i / 34, cc = i % 34;
        int A = A0 - 1 + rr, C = C0 - 1 + cc;
        tile[rr][cc] = (A >= 0 && A < NYX && C >= 0 && C < NYX)
                       ? ub[(size_t)A * NYX + C] : 0.0f;
    }
    __syncthreads();
    int a = threadIdx.y, c = threadIdx.x;
    float u0 = tile[a + 1][c + 1];
    float xp = tile[a + 2][c + 1], xm = tile[a][c + 1];
    float yp = tile[a + 1][c + 2], ym = tile[a + 1][c];
    float pp = tile[a + 2][c + 2], pm = tile[a + 2][c];
    float mp = tile[a][c + 2],     mm = tile[a][c];
    float dx  = 0.5f * (xp - xm);
    float dy  = 0.5f * (yp - ym);
    float dxx = xp - 2.0f * u0 + xm;
    float dyy = yp - 2.0f * u0 + ym;
    float dxy = 0.25f * (pp - pm - mp + mm);

    int s = (A0 + a) * NYX + (C0 + c);
    size_t pl = (size_t)bt * SP + s;
    const float* pb = g_p3 + (size_t)b * C3 * SP + s;
    float gm = sp10(pb[(size_t)(27 + t) * SP]);
    float vx = pb[(size_t)(36 + t) * SP];
    float vy = pb[(size_t)(45 + t) * SP];
    float kap = g_kg[pl];
    float m1  = g_m1[pl];
    float m2  = g_m2[pl];

    float r = u0 + kap * kap * u0 + m1 * dx + m2 * dy
            - ((gm + vx * vx) * dxx + 2.0f * vx * vy * dxy + (gm + vy * vy) * dyy);
    og[pl] = r;
}

// ---------------------------------------------------------------------------
__global__ void qx_reduce_k() {
    __shared__ float sm[256];
    int b = blockIdx.y;
    size_t base = (size_t)blockIdx.x * 4096;
    const float* xb = g_xg + (size_t)b * NT * SP;
    const float* wb = g_w  + (size_t)b * NT * SP;
    const float* vb = g_v  + (size_t)b * NT * SP;
    float sum = 0.0f;
    for (int i = threadIdx.x; i < 4096; i += 256) {
        size_t e = base + i;
        int t = (int)(e >> 16);
        int s = (int)(e & (SP - 1));
        float q;
        if (t == 0)       q = vb[s] - wb[SP + s];
        else if (t == 8)  q = -wb[7 * SP + s] + vb[8 * (size_t)SP + s];
        else              q = -wb[(size_t)(t - 1) * SP + s] + vb[e] + xb[e]
                              - wb[(size_t)(t + 1) * SP + s];
        sum += xb[e] * q;
    }
    sm[threadIdx.x] = sum;
    __syncthreads();
    for (int st = 128; st > 0; st >>= 1) {
        if (threadIdx.x < st) sm[threadIdx.x] += sm[threadIdx.x + st];
        __syncthreads();
    }
    if (threadIdx.x == 0) g_part[b * 160 + blockIdx.x] = sm[0];
}

__global__ void final_reduce_k(float* __restrict__ out) {
    int b = threadIdx.x;
    if (b < NB) {
        float s = 0.0f;
        for (int i = 0; i < 144; i++) s += g_part[b * 160 + i];
        out[OFF_XOUT + b] = s;
    }
}

// ---------------------------------------------------------------------------
extern "C" void kernel_launch(void* const* d_in, const int* in_sizes, int n_in,
                              void* d_out, int out_size) {
    const float* x  = (const float*)d_in[0];
    const float* w1 = (const float*)d_in[4];
    const float* w2 = (const float*)d_in[5];
    const float* w3 = (const float*)d_in[6];
    float* out = (float*)d_out;

    float *p1, *p2, *p3, *xg, *wg, *vg;
    cudaGetSymbolAddress((void**)&p1, g_p1);
    cudaGetSymbolAddress((void**)&p2, g_p2);
    cudaGetSymbolAddress((void**)&p3, g_p3);
    cudaGetSymbolAddress((void**)&xg, g_xg);
    cudaGetSymbolAddress((void**)&wg, g_w);
    cudaGetSymbolAddress((void**)&vg, g_v);

    // conv1: CIN=9,  MT=1, KS=6,  WOFF=0 ; conv2: CIN=10, MT=2, KS=6, WOFF=6 ;
    // conv3: CIN=20, MT=4, KS=12, WOFF=18
    const int smem1 = (9  * 3 + 1) * 258 * 4 + 6  * 16 * 4;   // 29,280
    const int smem2 = (10 * 3 + 1) * 258 * 4 + 6  * 16 * 4;   // 32,376
    const int smem3 = (20 * 3 + 1) * 258 * 4 + 12 * 16 * 4;   // 63,720
    cudaFuncSetAttribute((const void*)conv_mma_k<9,  true,  1, 6,  C1, 0,  4>, cudaFuncAttributeMaxDynamicSharedMemorySize, smem1);
    cudaFuncSetAttribute((const void*)conv_mma_k<10, true,  2, 6,  C2, 6,  3>, cudaFuncAttributeMaxDynamicSharedMemorySize, smem2);
    cudaFuncSetAttribute((const void*)conv_mma_k<20, false, 4, 12, C3, 18, 2>, cudaFuncAttributeMaxDynamicSharedMemorySize, smem3);

    // 1: weight prep
    prep_w_k<<<9, 256>>>(w1, w2, w3);
    // 2,3,4: conv chain (conv3 in the profiled 4th slot)
    conv_mma_k<9,  true,  1, 6,  C1, 0,  4><<<dim3(1, 256, NB), dim3(32, 8), smem1>>>(x,  p1);
    conv_mma_k<10, true,  2, 6,  C2, 6,  3><<<dim3(1, 256, NB), dim3(32, 8), smem2>>>(p1, p2);
    conv_mma_k<20, false, 4, 12, C3, 18, 2><<<dim3(1, 256, NB), dim3(32, 8), smem3>>>(p2, p3);

    // independent of convs
    transpose_k<<<dim3(8, 8, NB * NT), dim3(32, 8)>>>(x);

    // epilogues
    epiH_k<<<(NB * SP) / 256, 256>>>(out);
    epiA_scramble_k<<<dim3(256, NB), 256>>>(out);

    // PDE pipeline
    applyM_k<<<dim3(8, 32, NB * NT), dim3(32, 8)>>>(xg, wg);
    applyM_k<<<dim3(8, 32, NB * NT), dim3(32, 8)>>>(wg, vg);
    qx_reduce_k<<<dim3(144, NB), 256>>>();
    final_reduce_k<<<1, 32>>>(out);
}

// round 11
// speedup vs baseline: 1.1943x; 1.0137x over previous
#include <cuda_runtime.h>
#include <cuda_bf16.h>
#include <cstdint>

#define NB 16
#define NT 9
#define NYX 256
#define SP 65536
#define C1 10
#define C2 20
#define C3 54

#define OFF_XOUT 0
#define OFF_KAP  16
#define OFF_M    9437200
#define OFF_H    28311568

#define TSK 288   // skewed tile row stride (multiple of 32 banks)

__device__ float g_p1[NB * C1 * SP];
__device__ float g_p2[NB * C2 * SP];
__device__ float g_p3[NB * C3 * SP];
__device__ float g_xg[NB * NT * SP];
__device__ float g_w [NB * NT * SP];
__device__ float g_v [NB * NT * SP];
__device__ float g_kg [NB * NT * SP];
__device__ float g_m1 [NB * NT * SP];
__device__ float g_m2 [NB * NT * SP];
__device__ float g_part[NB * 160];
// bf16 A-fragments (hi,lo uint4 pairs). slots: conv1 0..5 (MT1,KS6),
// conv2 6..17 (MT2,KS6), conv3 18..65 (MT4,KS12). 66 slots x 32 lanes x 2.
__device__ uint4 g_wfrag[66 * 32 * 2];

__device__ __forceinline__ float sp10(float x) {
    float z = 10.0f * x;
    return (fmaxf(z, 0.0f) + log1pf(expf(-fabsf(z)))) * 0.1f;
}
// pack (lo, hi) f32 -> bf16x2 (lo in low half)
__device__ __forceinline__ uint32_t bfpack(float lo, float hi) {
    uint32_t r; asm("cvt.rn.bf16x2.f32 %0, %1, %2;" : "=r"(r) : "f"(hi), "f"(lo));
    return r;
}
__device__ __forceinline__ float bf_lo(uint32_t h) { return __uint_as_float(h << 16); }
__device__ __forceinline__ float bf_hi(uint32_t h) { return __uint_as_float(h & 0xFFFF0000u); }

__device__ __forceinline__ void mma_bf16(float* d, const uint32_t* a, const uint32_t* b) {
    asm("mma.sync.aligned.m16n8k16.row.col.f32.bf16.bf16.f32 "
        "{%0,%1,%2,%3}, {%4,%5,%6,%7}, {%8,%9}, {%0,%1,%2,%3};"
        : "+f"(d[0]), "+f"(d[1]), "+f"(d[2]), "+f"(d[3])
        : "r"(a[0]), "r"(a[1]), "r"(a[2]), "r"(a[3]), "r"(b[0]), "r"(b[1]));
}

// ---------------------------------------------------------------------------
// Prep: weights -> bf16 m16n8k16 A-fragments, hi/lo split.
// ---------------------------------------------------------------------------
__global__ void prep_w_k(const float* __restrict__ w1,
                         const float* __restrict__ w2,
                         const float* __restrict__ w3) {
    int idx = blockIdx.x * blockDim.x + threadIdx.x;
    if (idx >= 66 * 32) return;
    int lane = idx & 31;
    int slot = idx >> 5;
    const float* w; int K, COUT, mt, ks;
    if (slot < 6)       { w = w1; K = 81;  COUT = C1; mt = 0;               ks = slot; }
    else if (slot < 18) { w = w2; K = 90;  COUT = C2; int s = slot - 6;  mt = s / 6;  ks = s % 6; }
    else                { w = w3; K = 180; COUT = C3; int s = slot - 18; mt = s / 12; ks = s % 12; }
    int g = lane >> 2, tig = lane & 3;
    uint32_t hi[4], lo[4];
#pragma unroll
    for (int i = 0; i < 4; i++) {
        int row = mt * 16 + g + (i & 1) * 8;
        int k   = ks * 16 + (i >> 1) * 8 + 2 * tig;
        float w0 = (row < COUT && k     < K) ? w[row * K + k]     : 0.0f;
        float w1v = (row < COUT && k + 1 < K) ? w[row * K + k + 1] : 0.0f;
        uint32_t h = bfpack(w0, w1v);
        hi[i] = h;
        lo[i] = bfpack(w0 - bf_lo(h), w1v - bf_hi(h));
    }
    int base = (slot * 32 + lane) * 2;
    g_wfrag[base]     = make_uint4(hi[0], hi[1], hi[2], hi[3]);
    g_wfrag[base + 1] = make_uint4(lo[0], lo[1], lo[2], lo[3]);
}

// ---------------------------------------------------------------------------
// Generic conv3x3 via bf16 m16n8k16 tensor MMA, 3-pass (hi/lo split).
// Skewed smem tile: row R (=ci*3+ky) at R*288 + 8*ky + col  -> the four
// tig tap-segments of each B-fragment LDS land on disjoint bank ranges.
// ---------------------------------------------------------------------------
template <int CIN, bool RELU_IN, int MT, int KS, int COUT, int WOFF, int MAXB>
__global__ void __launch_bounds__(256, MAXB)
conv_mma_k(const float* __restrict__ in, float* __restrict__ out) {
    extern __shared__ float sh[];
    const int ZR = CIN * 3;
    float* tile = sh;                         // (CIN*3+1)*TSK floats
    int*   koff = (int*)(sh + (ZR + 1) * TSK);

    const int b  = blockIdx.z;
    const int y0 = blockIdx.y;
    const int tid = threadIdx.y * 32 + threadIdx.x;

    const float* inb = in + (size_t)b * CIN * SP;
    for (int idx = tid; idx < CIN * 3 * 258; idx += 256) {
        int c  = idx % 258;
        int rr = (idx / 258) % 3;             // ky
        int ci = idx / 774;
        int gy = y0 - 1 + rr;
        int gx = c - 1;
        float v = 0.0f;
        if (gy >= 0 && gy < NYX && gx >= 0 && gx < NYX) {
            v = inb[ci * SP + gy * NYX + gx];
            if (RELU_IN) v = fmaxf(v, 0.0f);
        }
        tile[(ci * 3 + rr) * TSK + 8 * rr + c] = v;
    }
    for (int i = tid; i < TSK; i += 256) tile[ZR * TSK + i] = 0.0f;
    for (int k = tid; k < KS * 16; k += 256) {
        if (k < CIN * 9) {
            int ci = k / 9, r = k % 9;
            int ky = r / 3;
            koff[k] = (ci * 3 + ky) * TSK + 8 * ky + (r % 3);
        } else {
            koff[k] = ZR * TSK;
        }
    }
    __syncthreads();

    const int warp = threadIdx.y;
    const int lane = threadIdx.x;
    const int g = lane >> 2, tig = lane & 3;
    const int nbase = warp * 32;

    float acc[MT][4][4];
#pragma unroll
    for (int m = 0; m < MT; m++)
#pragma unroll
        for (int n = 0; n < 4; n++)
#pragma unroll
            for (int q = 0; q < 4; q++) acc[m][n][q] = 0.0f;

    for (int ks = 0; ks < KS; ks++) {
        int o00 = koff[ks * 16 + 2 * tig];
        int o01 = koff[ks * 16 + 2 * tig + 1];
        int o10 = koff[ks * 16 + 8 + 2 * tig];
        int o11 = koff[ks * 16 + 8 + 2 * tig + 1];
        uint32_t bhi[4][2], blo[4][2];
#pragma unroll
        for (int nt = 0; nt < 4; nt++) {
            int n = nbase + nt * 8 + g;
            float x00 = tile[o00 + n], x01 = tile[o01 + n];
            float x10 = tile[o10 + n], x11 = tile[o11 + n];
            uint32_t h0 = bfpack(x00, x01);
            uint32_t h1 = bfpack(x10, x11);
            bhi[nt][0] = h0;
            bhi[nt][1] = h1;
            blo[nt][0] = bfpack(x00 - bf_lo(h0), x01 - bf_hi(h0));
            blo[nt][1] = bfpack(x10 - bf_lo(h1), x11 - bf_hi(h1));
        }
#pragma unroll
        for (int mt = 0; mt < MT; mt++) {
            int base = ((WOFF + mt * KS + ks) * 32 + lane) * 2;
            uint4 ah = g_wfrag[base];
            uint4 al = g_wfrag[base + 1];
            uint32_t ahi[4] = { ah.x, ah.y, ah.z, ah.w };
            uint32_t alo[4] = { al.x, al.y, al.z, al.w };
#pragma unroll
            for (int nt = 0; nt < 4; nt++) {
                mma_bf16(acc[mt][nt], ahi, bhi[nt]);
                mma_bf16(acc[mt][nt], ahi, blo[nt]);
                mma_bf16(acc[mt][nt], alo, bhi[nt]);
            }
        }
    }

#pragma unroll
    for (int mt = 0; mt < MT; mt++) {
        int co0 = mt * 16 + g;
#pragma unroll
        for (int nt = 0; nt < 4; nt++) {
            int px = nbase + nt * 8 + 2 * tig;
            float* op = out + ((size_t)b * COUT + co0) * SP + (size_t)y0 * NYX + px;
            if (co0 < COUT)
                *reinterpret_cast<float2*>(op) = make_float2(acc[mt][nt][0], acc[mt][nt][1]);
            if (co0 + 8 < COUT)
                *reinterpret_cast<float2*>(op + (size_t)8 * SP) = make_float2(acc[mt][nt][2], acc[mt][nt][3]);
        }
    }
}

// ---------------------------------------------------------------------------
// kappa_r + m_r outputs AND kg/m1/m2 plane grids, via smem staging.
// ---------------------------------------------------------------------------
__global__ void epiA_scramble_k(float* __restrict__ out) {
    __shared__ float shk[2304], shm1[2304], shm2[2304];
    int b = blockIdx.y;
    int chunk = blockIdx.x;
    int L0 = chunk * 2304;
    int s0 = chunk * 256;
    const float* src = g_p3 + (size_t)b * C3 * SP;
    float* okap = out + OFF_KAP + (size_t)b * 9 * SP;
    float* om   = out + OFF_M   + (size_t)b * 18 * SP;
#pragma unroll
    for (int it = 0; it < 9; ++it) {
        int i = it * 256 + threadIdx.x;
        int L = L0 + i;
        float k  = sp10(src[L]);
        float m1 = src[9 * SP + L];
        float m2 = src[18 * SP + L];
        shk[i] = k; shm1[i] = m1; shm2[i] = m2;
        okap[L] = k;
        om[L] = m1;
        om[9 * SP + L] = m2;
    }
    __syncthreads();
#pragma unroll
    for (int it = 0; it < 9; ++it) {
        int i = it * 256 + threadIdx.x;
        int so = i & 255;
        int t = i >> 8;
        int si = 9 * so + t;
        size_t dst = ((size_t)b * 9 + t) * SP + s0 + so;
        g_kg[dst] = shk[si];
        g_m1[dst] = shm1[si];
        g_m2[dst] = shm2[si];
    }
}

// ---------------------------------------------------------------------------
__global__ void epiH_k(float* __restrict__ out) {
    int gid = blockIdx.x * blockDim.x + threadIdx.x;
    int b = gid >> 16;
    int s = gid & (SP - 1);
    const float* pb = g_p3 + (size_t)b * C3 * SP + s;
    float gm[NT], vx[NT], vy[NT];
#pragma unroll
    for (int t = 0; t < NT; t++) {
        gm[t] = sp10(pb[(size_t)(27 + t) * SP]);
        vx[t] = pb[(size_t)(36 + t) * SP];
        vy[t] = pb[(size_t)(45 + t) * SP];
    }
    const size_t PLANE = (size_t)SP * NT;
    size_t base = OFF_H + (size_t)b * 4 * PLANE + (size_t)s * NT;
#pragma unroll
    for (int t = 0; t < NT; t++) out[base + t] = gm[t] + vx[t] * vx[t];
#pragma unroll
    for (int t = 0; t < NT; t++) {
        float xy = vx[t] * vy[t];
        out[base + PLANE + t]     = xy;
        out[base + 2 * PLANE + t] = xy;
    }
#pragma unroll
    for (int t = 0; t < NT; t++) out[base + 3 * PLANE + t] = gm[t] + vy[t] * vy[t];
}

// ---------------------------------------------------------------------------
__global__ void transpose_k(const float* __restrict__ x) {
    __shared__ float tile[32][33];
    int b = blockIdx.z / NT, t = blockIdx.z % NT;
    const float* xb = x + ((size_t)b * NT + t) * SP;
    float* og = g_xg + ((size_t)b * NT + t) * SP;
    int Y0 = blockIdx.y * 32, X0 = blockIdx.x * 32;
#pragma unroll
    for (int k = 0; k < 4; k++) {
        int row = threadIdx.y + k * 8;
        tile[row][threadIdx.x] = xb[(size_t)(Y0 + row) * NYX + X0 + threadIdx.x];
    }
    __syncthreads();
#pragma unroll
    for (int k = 0; k < 4; k++) {
        int row = threadIdx.y + k * 8;
        og[(size_t)(X0 + row) * NYX + Y0 + threadIdx.x] = tile[threadIdx.x][row];
    }
}

// ---------------------------------------------------------------------------
__global__ void applyM_k(const float* __restrict__ u, float* __restrict__ og) {
    __shared__ float tile[10][36];
    int bt = blockIdx.z;
    int b = bt / NT, t = bt % NT;
    int A0 = blockIdx.y * 8, C0 = blockIdx.x * 32;
    const float* ub = u + (size_t)bt * SP;
    int tid = threadIdx.y * 32 + threadIdx.x;
    for (int i = tid; i < 10 * 34; i += 256) {
        int rr = i / 34, cc = i % 34;
        int A = A0 - 1 + rr, C = C0 - 1 + cc;
        tile[rr][cc] = (A >= 0 && A < NYX && C >= 0 && C < NYX)
                       ? ub[(size_t)A * NYX + C] : 0.0f;
    }
    __syncthreads();
    int a = threadIdx.y, c = threadIdx.x;
    float u0 = tile[a + 1][c + 1];
    float xp = tile[a + 2][c + 1], xm = tile[a][c + 1];
    float yp = tile[a + 1][c + 2], ym = tile[a + 1][c];
    float pp = tile[a + 2][c + 2], pm = tile[a + 2][c];
    float mp = tile[a][c + 2],     mm = tile[a][c];
    float dx  = 0.5f * (xp - xm);
    float dy  = 0.5f * (yp - ym);
    float dxx = xp - 2.0f * u0 + xm;
    float dyy = yp - 2.0f * u0 + ym;
    float dxy = 0.25f * (pp - pm - mp + mm);

    int s = (A0 + a) * NYX + (C0 + c);
    size_t pl = (size_t)bt * SP + s;
    const float* pb = g_p3 + (size_t)b * C3 * SP + s;
    float gm = sp10(pb[(size_t)(27 + t) * SP]);
    float vx = pb[(size_t)(36 + t) * SP];
    float vy = pb[(size_t)(45 + t) * SP];
    float kap = g_kg[pl];
    float m1  = g_m1[pl];
    float m2  = g_m2[pl];

    float r = u0 + kap * kap * u0 + m1 * dx + m2 * dy
            - ((gm + vx * vx) * dxx + 2.0f * vx * vy * dxy + (gm + vy * vy) * dyy);
    og[pl] = r;
}

// ---------------------------------------------------------------------------
__global__ void qx_reduce_k() {
    __shared__ float sm[256];
    int b = blockIdx.y;
    size_t base = (size_t)blockIdx.x * 4096;
    const float* xb = g_xg + (size_t)b * NT * SP;
    const float* wb = g_w  + (size_t)b * NT * SP;
    const float* vb = g_v  + (size_t)b * NT * SP;
    float sum = 0.0f;
    for (int i = threadIdx.x; i < 4096; i += 256) {
        size_t e = base + i;
        int t = (int)(e >> 16);
        int s = (int)(e & (SP - 1));
        float q;
        if (t == 0)       q = vb[s] - wb[SP + s];
        else if (t == 8)  q = -wb[7 * SP + s] + vb[8 * (size_t)SP + s];
        else              q = -wb[(size_t)(t - 1) * SP + s] + vb[e] + xb[e]
                              - wb[(size_t)(t + 1) * SP + s];
        sum += xb[e] * q;
    }
    sm[threadIdx.x] = sum;
    __syncthreads();
    for (int st = 128; st > 0; st >>= 1) {
        if (threadIdx.x < st) sm[threadIdx.x] += sm[threadIdx.x + st];
        __syncthreads();
    }
    if (threadIdx.x == 0) g_part[b * 160 + blockIdx.x] = sm[0];
}

__global__ void final_reduce_k(float* __restrict__ out) {
    int b = threadIdx.x;
    if (b < NB) {
        float s = 0.0f;
        for (int i = 0; i < 144; i++) s += g_part[b * 160 + i];
        out[OFF_XOUT + b] = s;
    }
}

// ---------------------------------------------------------------------------
extern "C" void kernel_launch(void* const* d_in, const int* in_sizes, int n_in,
                              void* d_out, int out_size) {
    const float* x  = (const float*)d_in[0];
    const float* w1 = (const float*)d_in[4];
    const float* w2 = (const float*)d_in[5];
    const float* w3 = (const float*)d_in[6];
    float* out = (float*)d_out;

    float *p1, *p2, *p3, *xg, *wg, *vg;
    cudaGetSymbolAddress((void**)&p1, g_p1);
    cudaGetSymbolAddress((void**)&p2, g_p2);
    cudaGetSymbolAddress((void**)&p3, g_p3);
    cudaGetSymbolAddress((void**)&xg, g_xg);
    cudaGetSymbolAddress((void**)&wg, g_w);
    cudaGetSymbolAddress((void**)&vg, g_v);

    // conv1: CIN=9,  MT=1, KS=6,  WOFF=0 ; conv2: CIN=10, MT=2, KS=6, WOFF=6 ;
    // conv3: CIN=20, MT=4, KS=12, WOFF=18. Skewed tile stride TSK=288.
    const int smem1 = (9  * 3 + 1) * TSK * 4 + 6  * 16 * 4;   // 32,640
    const int smem2 = (10 * 3 + 1) * TSK * 4 + 6  * 16 * 4;   // 36,096
    const int smem3 = (20 * 3 + 1) * TSK * 4 + 12 * 16 * 4;   // 71,040
    cudaFuncSetAttribute((const void*)conv_mma_k<9,  true,  1, 6,  C1, 0,  4>, cudaFuncAttributeMaxDynamicSharedMemorySize, smem1);
    cudaFuncSetAttribute((const void*)conv_mma_k<10, true,  2, 6,  C2, 6,  3>, cudaFuncAttributeMaxDynamicSharedMemorySize, smem2);
    cudaFuncSetAttribute((const void*)conv_mma_k<20, false, 4, 12, C3, 18, 2>, cudaFuncAttributeMaxDynamicSharedMemorySize, smem3);

    // 1: weight prep
    prep_w_k<<<9, 256>>>(w1, w2, w3);
    // 2,3,4: conv chain (conv3 in the profiled slot)
    conv_mma_k<9,  true,  1, 6,  C1, 0,  4><<<dim3(1, 256, NB), dim3(32, 8), smem1>>>(x,  p1);
    conv_mma_k<10, true,  2, 6,  C2, 6,  3><<<dim3(1, 256, NB), dim3(32, 8), smem2>>>(p1, p2);
    conv_mma_k<20, false, 4, 12, C3, 18, 2><<<dim3(1, 256, NB), dim3(32, 8), smem3>>>(p2, p3);

    // independent of convs
    transpose_k<<<dim3(8, 8, NB * NT), dim3(32, 8)>>>(x);

    // epilogues
    epiH_k<<<(NB * SP) / 256, 256>>>(out);
    epiA_scramble_k<<<dim3(256, NB), 256>>>(out);

    // PDE pipeline
    applyM_k<<<dim3(8, 32, NB * NT), dim3(32, 8)>>>(xg, wg);
    applyM_k<<<dim3(8, 32, NB * NT), dim3(32, 8)>>>(wg, vg);
    qx_reduce_k<<<dim3(144, NB), 256>>>();
    final_reduce_k<<<1, 32>>>(out);
}